// round 5
// baseline (speedup 1.0000x reference)
#include <cuda_runtime.h>

// Fixed problem shape
#define NB 2048
#define ND 16384
#define RSPLIT 64
#define ROWS_PER (NB / RSPLIT)        // 32 rows per partial block
#define FIN_BLOCKS 32                 // 32 * 256 thr * 2 cols = 16384
#define PUN_WARPS 16                  // warps per punish block (1 row each)
#define PUN_BLOCKS (NB / PUN_WARPS)   // 128
#define NF4 (ND / 4)                  // 4096 float4 per row

// Scratch (__device__ globals; no allocation allowed)
__device__ float g_psum[RSPLIT * ND];
__device__ float g_psq [RSPLIT * ND];
__device__ float g_nmean[ND];
__device__ float g_nvar [ND];
__device__ float g_varpart[FIN_BLOCKS];
__device__ float g_addend;
__device__ int   g_fcnt;              // zero-init; self-resetting

// ---------------------------------------------------------------------------
// Pass 1: partial column stats + bulk copy h -> out.
// grid = (ND/1024, RSPLIT), block = 256. h read evict-first (__ldcs) so the
// default-policy out writes (write-allocate) own L2 for punish's re-read.
// ---------------------------------------------------------------------------
__global__ void __launch_bounds__(256) k_colstats_copy(const float* __restrict__ h,
                                                       float* __restrict__ out) {
    const int c  = (blockIdx.x * 256 + threadIdx.x) * 4;
    const int r0 = blockIdx.y * ROWS_PER;
    float4 s = make_float4(0.f, 0.f, 0.f, 0.f);
    float4 q = make_float4(0.f, 0.f, 0.f, 0.f);
    const float4* hp = reinterpret_cast<const float4*>(h   + (size_t)r0 * ND + c);
    float4*       op = reinterpret_cast<float4*>      (out + (size_t)r0 * ND + c);
    const size_t stride4 = ND / 4;
#pragma unroll 8
    for (int r = 0; r < ROWS_PER; ++r) {
        float4 v = __ldcs(&hp[(size_t)r * stride4]);
        op[(size_t)r * stride4] = v;      // default policy: stays in L2
        s.x += v.x;       s.y += v.y;       s.z += v.z;       s.w += v.w;
        q.x += v.x * v.x; q.y += v.y * v.y; q.z += v.z * v.z; q.w += v.w * v.w;
    }
    *reinterpret_cast<float4*>(g_psum + (size_t)blockIdx.y * ND + c) = s;
    *reinterpret_cast<float4*>(g_psq  + (size_t)blockIdx.y * ND + c) = q;
}

// ---------------------------------------------------------------------------
// Pass 2: finish stats -> new_mean, new_var; last block computes addend.
// grid = FIN_BLOCKS (32), block = 256, 2 cols/thread.
// ---------------------------------------------------------------------------
__global__ void __launch_bounds__(256) k_colstats_finish(const float* __restrict__ hmean,
                                                         const float* __restrict__ hvar) {
    const int c = (blockIdx.x * 256 + threadIdx.x) * 2;
    float2 s = make_float2(0.f, 0.f);
    float2 q = make_float2(0.f, 0.f);
#pragma unroll 8
    for (int i = 0; i < RSPLIT; ++i) {
        float2 a = *reinterpret_cast<const float2*>(g_psum + (size_t)i * ND + c);
        float2 b = *reinterpret_cast<const float2*>(g_psq  + (size_t)i * ND + c);
        s.x += a.x; s.y += a.y;
        q.x += b.x; q.y += b.y;
    }
    const float invB    = 1.0f / (float)NB;
    const float U       = 10.0f;
    const float inv11   = 1.0f / 11.0f;
    const float inv1p1  = 1.0f / 1.1f;
    const float invDen  = 1.0f / (U + 1.0f - invB);
    const float coefOld = U - invB;

    float2 hm = *reinterpret_cast<const float2*>(hmean + c);
    float2 hv = *reinterpret_cast<const float2*>(hvar  + c);

    float2 nm, nv;
    {
        float mu, var, d;
        mu = s.x * invB; var = q.x * invB - mu * mu; d = mu - hm.x;
        nv.x = (hv.x * coefOld + var + d * d * inv1p1) * invDen;
        nm.x = (hm.x * U + mu) * inv11;
        mu = s.y * invB; var = q.y * invB - mu * mu; d = mu - hm.y;
        nv.y = (hv.y * coefOld + var + d * d * inv1p1) * invDen;
        nm.y = (hm.y * U + mu) * inv11;
    }
    *reinterpret_cast<float2*>(g_nmean + c) = nm;
    *reinterpret_cast<float2*>(g_nvar  + c) = nv;

    __shared__ float sred[256];
    sred[threadIdx.x] = nv.x + nv.y;
    __syncthreads();
    for (int off = 128; off > 0; off >>= 1) {
        if (threadIdx.x < off) sred[threadIdx.x] += sred[threadIdx.x + off];
        __syncthreads();
    }

    __shared__ int is_last;
    if (threadIdx.x == 0) {
        g_varpart[blockIdx.x] = sred[0];
        __threadfence();
        int old = atomicAdd(&g_fcnt, 1);
        is_last = (old == FIN_BLOCKS - 1) ? 1 : 0;
    }
    __syncthreads();
    if (is_last && threadIdx.x < 32) {
        __threadfence();
        float v = g_varpart[threadIdx.x];   // FIN_BLOCKS == 32
#pragma unroll
        for (int off = 16; off > 0; off >>= 1)
            v += __shfl_down_sync(0xFFFFFFFFu, v, off);
        if (threadIdx.x == 0) {
            g_addend = (v / (float)ND) * 0.01f;
            g_fcnt = 0;                     // reset for next graph replay
        }
    }
}

// ---------------------------------------------------------------------------
// Pass 3: read-only argmax over out (== h), warp-per-row, mean/inv in smem.
// grid = 128, block = 512 (16 warps x 1 row, looped once: 16 rows/block).
// Dynamic smem 128KB: [0..ND) mean, [ND..2*ND) inv. No barriers/atomics in
// the hot loop. Winner fixup: lane 0 writes out[row][w] = mean[w].
// ---------------------------------------------------------------------------
__device__ __forceinline__ float score_of(float hv, float m, float iv) {
    float d = __fadd_rn(hv, -m);
    return __fmul_rn(__fmul_rn(d, d), iv);
}

__global__ void __launch_bounds__(512) k_punish(float* out) {
    extern __shared__ float smem[];
    float* sm_mean = smem;
    float* sm_inv  = smem + ND;
    const int tid = threadIdx.x;

    // Fill smem: mean + inv = 1/(nvar + addend). 4096 float4 per array.
    {
        const float a = g_addend;
        const float4* m4 = reinterpret_cast<const float4*>(g_nmean);
        const float4* v4 = reinterpret_cast<const float4*>(g_nvar);
        float4* smm = reinterpret_cast<float4*>(sm_mean);
        float4* smi = reinterpret_cast<float4*>(sm_inv);
#pragma unroll
        for (int j = tid; j < NF4; j += 512) {
            float4 m = __ldg(&m4[j]);
            float4 v = __ldg(&v4[j]);
            float4 iv;
            iv.x = 1.0f / (v.x + a);
            iv.y = 1.0f / (v.y + a);
            iv.z = 1.0f / (v.z + a);
            iv.w = 1.0f / (v.w + a);
            smm[j] = m;
            smi[j] = iv;
        }
    }
    __syncthreads();

    const int wid  = tid >> 5;
    const int lane = tid & 31;
    const int row  = blockIdx.x * PUN_WARPS + wid;

    const float4* orow = reinterpret_cast<const float4*>(out + (size_t)row * ND);
    const float4* smm  = reinterpret_cast<const float4*>(sm_mean);
    const float4* smi  = reinterpret_cast<const float4*>(sm_inv);

    float best = -1.0f;
    int   bj   = lane;          // winning float4 index (ascending per lane)

#pragma unroll
    for (int it = 0; it < NF4 / (32 * 8); ++it) {       // 16 iterations
        const int jb = it * 256 + lane;                 // 8 chunks of 32
        // front-batched global loads (512B/warp each -> deep MLP)
        float4 h0 = orow[jb];
        float4 h1 = orow[jb + 32];
        float4 h2 = orow[jb + 64];
        float4 h3 = orow[jb + 96];
        float4 h4 = orow[jb + 128];
        float4 h5 = orow[jb + 160];
        float4 h6 = orow[jb + 192];
        float4 h7 = orow[jb + 224];

#define SCORE_GROUP(HV, J)                                                     \
        {                                                                      \
            const int j_ = (J);                                                \
            float4 m_  = smm[j_];                                              \
            float4 iv_ = smi[j_];                                              \
            float mx_ = fmaxf(fmaxf(score_of((HV).x, m_.x, iv_.x),             \
                                    score_of((HV).y, m_.y, iv_.y)),            \
                              fmaxf(score_of((HV).z, m_.z, iv_.z),             \
                                    score_of((HV).w, m_.w, iv_.w)));           \
            if (mx_ > best) { best = mx_; bj = j_; }                           \
        }
        SCORE_GROUP(h0, jb)
        SCORE_GROUP(h1, jb + 32)
        SCORE_GROUP(h2, jb + 64)
        SCORE_GROUP(h3, jb + 96)
        SCORE_GROUP(h4, jb + 128)
        SCORE_GROUP(h5, jb + 160)
        SCORE_GROUP(h6, jb + 192)
        SCORE_GROUP(h7, jb + 224)
#undef SCORE_GROUP
    }

    // Resolve winning element inside the winning float4 (bitwise-identical
    // recompute; first match = lowest column, matching jnp.argmax ties).
    int bidx;
    {
        float4 hv = orow[bj];
        float4 m  = smm[bj];
        float4 iv = smi[bj];
        float s0 = score_of(hv.x, m.x, iv.x);
        float s1 = score_of(hv.y, m.y, iv.y);
        float s2 = score_of(hv.z, m.z, iv.z);
        bidx = bj * 4 + ((s0 == best) ? 0 : (s1 == best) ? 1 : (s2 == best) ? 2 : 3);
    }

    // Warp argmax: u64 key = score_bits<<32 | ~col  (max => max score, low col)
    unsigned long long key =
        ((unsigned long long)__float_as_uint(best) << 32) |
        (unsigned long long)(0xFFFFFFFFu - (unsigned)bidx);
#pragma unroll
    for (int off = 16; off > 0; off >>= 1) {
        unsigned long long o = __shfl_xor_sync(0xFFFFFFFFu, key, off);
        if (o > key) key = o;
    }
    if (lane == 0) {
        int w = (int)(0xFFFFFFFFu - (unsigned)(key & 0xFFFFFFFFull));
        out[(size_t)row * ND + w] = sm_mean[w];
    }
}

// ---------------------------------------------------------------------------
extern "C" void kernel_launch(void* const* d_in, const int* in_sizes, int n_in,
                              void* d_out, int out_size) {
    const float* h     = (const float*)d_in[0];
    const float* hmean = (const float*)d_in[1];
    const float* hvar  = (const float*)d_in[2];
    float* out = (float*)d_out;
    (void)in_sizes; (void)n_in; (void)out_size;

    const int smem_bytes = 2 * ND * (int)sizeof(float);   // 128 KB
    cudaFuncSetAttribute(k_punish, cudaFuncAttributeMaxDynamicSharedMemorySize,
                         smem_bytes);

    dim3 g1(ND / (256 * 4), RSPLIT);
    k_colstats_copy<<<g1, 256>>>(h, out);
    k_colstats_finish<<<FIN_BLOCKS, 256>>>(hmean, hvar);
    k_punish<<<PUN_BLOCKS, 512, smem_bytes>>>(out);
}

// round 6
// speedup vs baseline: 1.2947x; 1.2947x over previous
#include <cuda_runtime.h>

// Fixed problem shape
#define NB 2048
#define ND 16384
#define RSPLIT 64
#define ROWS_PER (NB / RSPLIT)        // 32 rows per partial block
#define FIN_BLOCKS 32                 // 32 * 256 thr * 2 cols = 16384
#define SI_BLOCKS 64                  // 64 * 256 = 16384 cols

// Scratch (__device__ globals; no allocation allowed)
__device__ float g_psum[RSPLIT * ND];
__device__ float g_psq [RSPLIT * ND];
__device__ float g_nmean[ND];
__device__ float g_nvar [ND];
__device__ float g_inv  [ND];
__device__ float g_varpart[FIN_BLOCKS];
__device__ float g_addend;
__device__ int   g_fcnt;              // zero-init; self-resetting

// ---------------------------------------------------------------------------
// Pass 1: per-(rowchunk, column) partial sum / sumsq.
// h read with DEFAULT policy (leave h resident in L2 for punish's reversed
// re-read); partial writes streaming so they don't evict h.
// grid = (ND/1024, RSPLIT), block = 256.
// ---------------------------------------------------------------------------
__global__ void __launch_bounds__(256) k_colstats_partial(const float* __restrict__ h) {
    const int c  = (blockIdx.x * 256 + threadIdx.x) * 4;
    const int r0 = blockIdx.y * ROWS_PER;
    float4 s = make_float4(0.f, 0.f, 0.f, 0.f);
    float4 q = make_float4(0.f, 0.f, 0.f, 0.f);
    const float4* hp = reinterpret_cast<const float4*>(h + (size_t)r0 * ND + c);
    const size_t stride4 = ND / 4;
#pragma unroll 8
    for (int r = 0; r < ROWS_PER; ++r) {
        float4 v = hp[(size_t)r * stride4];          // default: keep in L2
        s.x += v.x;       s.y += v.y;       s.z += v.z;       s.w += v.w;
        q.x += v.x * v.x; q.y += v.y * v.y; q.z += v.z * v.z; q.w += v.w * v.w;
    }
    __stcs(reinterpret_cast<float4*>(g_psum + (size_t)blockIdx.y * ND + c), s);
    __stcs(reinterpret_cast<float4*>(g_psq  + (size_t)blockIdx.y * ND + c), q);
}

// ---------------------------------------------------------------------------
// Pass 2: finish stats -> new_mean, new_var; last block computes addend.
// Partial reads streaming (don't evict h). grid = 32, block = 256.
// ---------------------------------------------------------------------------
__global__ void __launch_bounds__(256) k_colstats_finish(const float* __restrict__ hmean,
                                                         const float* __restrict__ hvar) {
    const int c = (blockIdx.x * 256 + threadIdx.x) * 2;
    float2 s = make_float2(0.f, 0.f);
    float2 q = make_float2(0.f, 0.f);
#pragma unroll 8
    for (int i = 0; i < RSPLIT; ++i) {
        float2 a = __ldcs(reinterpret_cast<const float2*>(g_psum + (size_t)i * ND + c));
        float2 b = __ldcs(reinterpret_cast<const float2*>(g_psq  + (size_t)i * ND + c));
        s.x += a.x; s.y += a.y;
        q.x += b.x; q.y += b.y;
    }
    const float invB    = 1.0f / (float)NB;
    const float U       = 10.0f;
    const float inv11   = 1.0f / 11.0f;
    const float inv1p1  = 1.0f / 1.1f;
    const float invDen  = 1.0f / (U + 1.0f - invB);
    const float coefOld = U - invB;

    float2 hm = *reinterpret_cast<const float2*>(hmean + c);
    float2 hv = *reinterpret_cast<const float2*>(hvar  + c);

    float2 nm, nv;
    {
        float mu, var, d;
        mu = s.x * invB; var = q.x * invB - mu * mu; d = mu - hm.x;
        nv.x = (hv.x * coefOld + var + d * d * inv1p1) * invDen;
        nm.x = (hm.x * U + mu) * inv11;
        mu = s.y * invB; var = q.y * invB - mu * mu; d = mu - hm.y;
        nv.y = (hv.y * coefOld + var + d * d * inv1p1) * invDen;
        nm.y = (hm.y * U + mu) * inv11;
    }
    *reinterpret_cast<float2*>(g_nmean + c) = nm;
    *reinterpret_cast<float2*>(g_nvar  + c) = nv;

    __shared__ float sred[256];
    sred[threadIdx.x] = nv.x + nv.y;
    __syncthreads();
    for (int off = 128; off > 0; off >>= 1) {
        if (threadIdx.x < off) sred[threadIdx.x] += sred[threadIdx.x + off];
        __syncthreads();
    }

    __shared__ int is_last;
    if (threadIdx.x == 0) {
        g_varpart[blockIdx.x] = sred[0];
        __threadfence();
        int old = atomicAdd(&g_fcnt, 1);
        is_last = (old == FIN_BLOCKS - 1) ? 1 : 0;
    }
    __syncthreads();
    if (is_last && threadIdx.x < 32) {
        __threadfence();
        float v = g_varpart[threadIdx.x];   // FIN_BLOCKS == 32
#pragma unroll
        for (int off = 16; off > 0; off >>= 1)
            v += __shfl_down_sync(0xFFFFFFFFu, v, off);
        if (threadIdx.x == 0) {
            g_addend = (v / (float)ND) * 0.01f;
            g_fcnt = 0;                     // reset for next graph replay
        }
    }
}

// ---------------------------------------------------------------------------
// Pass 3: inv = 1/(new_var + addend). grid = 64, block = 256, 1 col/thread.
// ---------------------------------------------------------------------------
__global__ void __launch_bounds__(256) k_scalar_inv() {
    const float a = g_addend;
    const int c = blockIdx.x * 256 + threadIdx.x;
    g_inv[c] = 1.0f / (g_nvar[c] + a);
}

// ---------------------------------------------------------------------------
// Pass 4: per-row copy + argmax, REVERSED row order (row = NB-1-blockIdx) so
// punish consumes h in the opposite order pass1 left it in L2 -> LRU hits.
// h loads __ldcs (read-once, keep L1 clean for mean/inv), out stores __stcs,
// mean/inv via __ldg (128KB total -> fits L1; ~14 blocks/SM share it).
// grid = NB, block = 256.
// ---------------------------------------------------------------------------
__device__ __forceinline__ float score_of(float hv, float m, float iv) {
    float d = __fadd_rn(hv, -m);
    return __fmul_rn(__fmul_rn(d, d), iv);
}

__global__ void __launch_bounds__(256) k_punish(const float* __restrict__ h,
                                                float* __restrict__ out) {
    const int row = NB - 1 - blockIdx.x;      // reversed traversal
    const int tid = threadIdx.x;

    const float4* hrow = reinterpret_cast<const float4*>(h   + (size_t)row * ND);
    float4*       orow = reinterpret_cast<float4*>      (out + (size_t)row * ND);
    const float4* m4p  = reinterpret_cast<const float4*>(g_nmean);
    const float4* i4p  = reinterpret_cast<const float4*>(g_inv);

    float best = -1.0f;   // scores >= 0
    int   bj   = tid;     // winning float4 index (ascending per thread)

#pragma unroll
    for (int it = 0; it < ND / (256 * 4 * 2); ++it) {   // 8 iterations, 2 chunks
        const int j0 = it * 512 + tid;
        const int j1 = j0 + 256;

        float4 h0 = __ldcs(&hrow[j0]);
        float4 h1 = __ldcs(&hrow[j1]);
        float4 m0 = __ldg(&m4p[j0]);
        float4 m1 = __ldg(&m4p[j1]);
        float4 v0 = __ldg(&i4p[j0]);
        float4 v1 = __ldg(&i4p[j1]);

        __stcs(&orow[j0], h0);
        __stcs(&orow[j1], h1);

        float mx;
        mx = fmaxf(fmaxf(score_of(h0.x, m0.x, v0.x), score_of(h0.y, m0.y, v0.y)),
                   fmaxf(score_of(h0.z, m0.z, v0.z), score_of(h0.w, m0.w, v0.w)));
        if (mx > best) { best = mx; bj = j0; }
        mx = fmaxf(fmaxf(score_of(h1.x, m1.x, v1.x), score_of(h1.y, m1.y, v1.y)),
                   fmaxf(score_of(h1.z, m1.z, v1.z), score_of(h1.w, m1.w, v1.w)));
        if (mx > best) { best = mx; bj = j1; }
    }

    // Resolve winning element in the winning float4 (bitwise-identical
    // recompute; first match = lowest column, matching jnp.argmax ties).
    int bidx;
    {
        float4 hv = __ldcs(&hrow[bj]);
        float4 m  = __ldg(&m4p[bj]);
        float4 iv = __ldg(&i4p[bj]);
        float s0 = score_of(hv.x, m.x, iv.x);
        float s1 = score_of(hv.y, m.y, iv.y);
        float s2 = score_of(hv.z, m.z, iv.z);
        bidx = bj * 4 + ((s0 == best) ? 0 : (s1 == best) ? 1 : (s2 == best) ? 2 : 3);
    }

    __shared__ float sbest[256];
    __shared__ int   sidx[256];
    sbest[tid] = best;
    sidx[tid]  = bidx;
    __syncthreads();
    for (int off = 128; off > 0; off >>= 1) {
        if (tid < off) {
            float ob = sbest[tid + off];
            int   oi = sidx[tid + off];
            if (ob > sbest[tid] || (ob == sbest[tid] && oi < sidx[tid])) {
                sbest[tid] = ob;
                sidx[tid]  = oi;
            }
        }
        __syncthreads();
    }
    if (tid == 0) {
        int w = sidx[0];
        out[(size_t)row * ND + w] = g_nmean[w];
    }
}

// ---------------------------------------------------------------------------
extern "C" void kernel_launch(void* const* d_in, const int* in_sizes, int n_in,
                              void* d_out, int out_size) {
    const float* h     = (const float*)d_in[0];
    const float* hmean = (const float*)d_in[1];
    const float* hvar  = (const float*)d_in[2];
    float* out = (float*)d_out;
    (void)in_sizes; (void)n_in; (void)out_size;

    dim3 g1(ND / (256 * 4), RSPLIT);
    k_colstats_partial<<<g1, 256>>>(h);
    k_colstats_finish<<<FIN_BLOCKS, 256>>>(hmean, hvar);
    k_scalar_inv<<<SI_BLOCKS, 256>>>();
    k_punish<<<NB, 256>>>(h, out);
}